// round 10
// baseline (speedup 1.0000x reference)
#include <cuda_runtime.h>

// MulticlassNeighborLayer: out[b,i,c] = 1.7159*tanh( (2/3) * (x[b,i-1]*W[i,c,0]
//                     + x[b,i]*W[i,c,1] + x[b,i+1]*W[i,c,2] + bias[i,c]) )
// B=64, N=16384 (circular), C=64. 268MB f32 output.
//
// FINAL (reproduced twice: 47.2us R7, 47.1us R9 — the session's two best):
// pinned at the L2-array write-stream cap. 557MB mandatory L2 traffic
// (268MB store-in + 268MB dirty-evict + ~21MB input) at the HW-measured,
// path-independent LTS ceiling (~6300 B/cyc) => ~46.5us analytical floor;
// this kernel runs at 99% of it. Profile invariant under store policy
// (cs/wt/default), LDS layout, occupancy (42-65%), grid shape (1024/2048),
// prologue order, and SW pipelining (which regressed and was reverted).
//
// Structure: 1024 CTAs x (16 cells x 64 classes); register-resident
// weights+bias pre-scaled by 2/3 (64x batch reuse, weights hit DRAM once);
// batch-major transposed smem x-tile so one LDS.128 serves 4 batches/tap;
// per-warp contiguous 512B float4 store lines; HW tanh.approx.f32
// (rel_err 4e-6, 250x under the 1e-3 threshold).

#define N_CELLS 16384
#define N_MASK  (N_CELLS - 1)
#define NUM_CLASSES 64
#define BATCH 64
#define ITILE 16
#define THREADS 256
#define BSTRIDE 68   // padded batch-major row stride (floats)

__device__ __forceinline__ float tanh_fast(float v) {
    float y;
    asm("tanh.approx.f32 %0, %1;" : "=f"(y) : "f"(v));
    return y;
}

__device__ __forceinline__ void st_cs_f4(float* p, float4 v) {
    asm volatile("st.global.cs.v4.f32 [%0], {%1,%2,%3,%4};"
                 :: "l"(p), "f"(v.x), "f"(v.y), "f"(v.z), "f"(v.w)
                 : "memory");
}

__global__ __launch_bounds__(THREADS)
void mcnl_kernel(const float* __restrict__ x,
                 const float* __restrict__ w,
                 const float* __restrict__ bias,
                 float* __restrict__ out)
{
    __shared__ float sxT[ITILE + 2][BSTRIDE];   // [k][b]

    const int tid = threadIdx.x;
    const int it  = tid >> 4;          // 0..15 : cell within tile
    const int c0  = (tid & 15) * 4;    // first class of this thread's 4
    const int i0  = blockIdx.x * ITILE;
    const int i   = i0 + it;

    // Weight/bias loads first: DRAM latency overlaps the halo gather.
    const float4* wp = reinterpret_cast<const float4*>(
        w + (size_t)i * NUM_CLASSES * 3 + (size_t)c0 * 3);
    float4 wa = wp[0];
    float4 wb = wp[1];
    float4 wc = wp[2];
    float4 bv = *reinterpret_cast<const float4*>(
        bias + (size_t)i * NUM_CLASSES + c0);

    // Cooperative x halo tile, transposed: sxT[k][b] = x[b, (i0-1+k) mod N]
    for (int j = tid; j < BATCH * (ITILE + 2); j += THREADS) {
        int b = j / (ITILE + 2);
        int k = j - b * (ITILE + 2);
        int gi = (i0 - 1 + k) & N_MASK;
        sxT[k][b] = x[b * N_CELLS + gi];
    }

    // Rearrange + pre-scale by 2/3.
    const float s = 2.0f / 3.0f;
    float tmp[12] = {wa.x, wa.y, wa.z, wa.w,
                     wb.x, wb.y, wb.z, wb.w,
                     wc.x, wc.y, wc.z, wc.w};
    float w0[4], w1[4], w2[4], bb[4];
    #pragma unroll
    for (int j = 0; j < 4; j++) {
        w0[j] = tmp[3 * j + 0] * s;
        w1[j] = tmp[3 * j + 1] * s;
        w2[j] = tmp[3 * j + 2] * s;
    }
    bb[0] = bv.x * s; bb[1] = bv.y * s; bb[2] = bv.z * s; bb[3] = bv.w * s;

    __syncthreads();

    float* outp = out + (size_t)i * NUM_CLASSES + c0;
    const size_t bstride = (size_t)N_CELLS * NUM_CLASSES;

    #pragma unroll 8
    for (int b = 0; b < BATCH; b += 4) {
        // One LDS.128 per tap covers 4 batches.
        float4 l4 = *reinterpret_cast<const float4*>(&sxT[it][b]);
        float4 c4 = *reinterpret_cast<const float4*>(&sxT[it + 1][b]);
        float4 r4 = *reinterpret_cast<const float4*>(&sxT[it + 2][b]);

        float ls[4] = {l4.x, l4.y, l4.z, l4.w};
        float cs[4] = {c4.x, c4.y, c4.z, c4.w};
        float rs[4] = {r4.x, r4.y, r4.z, r4.w};

        #pragma unroll
        for (int u = 0; u < 4; u++) {
            float o[4];
            #pragma unroll
            for (int j = 0; j < 4; j++) {
                float acc = fmaf(ls[u], w0[j],
                            fmaf(cs[u], w1[j],
                            fmaf(rs[u], w2[j], bb[j])));
                o[j] = 1.7159f * tanh_fast(acc);
            }
            st_cs_f4(outp + (size_t)(b + u) * bstride,
                     make_float4(o[0], o[1], o[2], o[3]));
        }
    }
}

extern "C" void kernel_launch(void* const* d_in, const int* in_sizes, int n_in,
                              void* d_out, int out_size) {
    const float* x    = (const float*)d_in[0];
    const float* w    = (const float*)d_in[1];
    const float* bias = (const float*)d_in[2];
    float* out = (float*)d_out;

    dim3 grid(N_CELLS / ITILE);   // 1024 CTAs
    dim3 block(THREADS);
    mcnl_kernel<<<grid, block>>>(x, w, bias, out);
}

// round 11
// speedup vs baseline: 1.0020x; 1.0020x over previous
#include <cuda_runtime.h>

// MulticlassNeighborLayer: out[b,i,c] = 1.7159*tanh( (2/3) * (x[b,i-1]*W[i,c,0]
//                     + x[b,i]*W[i,c,1] + x[b,i+1]*W[i,c,2] + bias[i,c]) )
// B=64, N=16384 (circular), C=64. 268MB f32 output.
//
// FINAL (reproduced 3x: 47.2/47.1/47.2us — session best): pinned at the
// L2-array write-stream cap. 557MB mandatory L2 traffic (268MB store-in +
// 268MB dirty-evict + ~21MB input) moves at ~11.2TB/s == the HW-measured
// path-independent LTS ceiling (~6300 B/cyc @ NAT). ~46.5us analytical
// floor; this kernel runs at 99% of it. Profile invariant under store
// policy (cs/wt/default), LDS layout, occupancy (42-65%), grid shape
// (1024/2048), prologue order; SW pipelining regressed and was reverted.
//
// Structure: 1024 CTAs x (16 cells x 64 classes); register-resident
// weights+bias pre-scaled by 2/3 (64x batch reuse, weights hit DRAM once);
// batch-major transposed smem x-tile so one LDS.128 serves 4 batches/tap;
// per-warp contiguous 512B float4 store lines; HW tanh.approx.f32
// (rel_err 4e-6, 250x under the 1e-3 threshold).

#define N_CELLS 16384
#define N_MASK  (N_CELLS - 1)
#define NUM_CLASSES 64
#define BATCH 64
#define ITILE 16
#define THREADS 256
#define BSTRIDE 68   // padded batch-major row stride (floats)

__device__ __forceinline__ float tanh_fast(float v) {
    float y;
    asm("tanh.approx.f32 %0, %1;" : "=f"(y) : "f"(v));
    return y;
}

__device__ __forceinline__ void st_cs_f4(float* p, float4 v) {
    asm volatile("st.global.cs.v4.f32 [%0], {%1,%2,%3,%4};"
                 :: "l"(p), "f"(v.x), "f"(v.y), "f"(v.z), "f"(v.w)
                 : "memory");
}

__global__ __launch_bounds__(THREADS)
void mcnl_kernel(const float* __restrict__ x,
                 const float* __restrict__ w,
                 const float* __restrict__ bias,
                 float* __restrict__ out)
{
    __shared__ float sxT[ITILE + 2][BSTRIDE];   // [k][b]

    const int tid = threadIdx.x;
    const int it  = tid >> 4;          // 0..15 : cell within tile
    const int c0  = (tid & 15) * 4;    // first class of this thread's 4
    const int i0  = blockIdx.x * ITILE;
    const int i   = i0 + it;

    // Weight/bias loads first: DRAM latency overlaps the halo gather.
    const float4* wp = reinterpret_cast<const float4*>(
        w + (size_t)i * NUM_CLASSES * 3 + (size_t)c0 * 3);
    float4 wa = wp[0];
    float4 wb = wp[1];
    float4 wc = wp[2];
    float4 bv = *reinterpret_cast<const float4*>(
        bias + (size_t)i * NUM_CLASSES + c0);

    // Cooperative x halo tile, transposed: sxT[k][b] = x[b, (i0-1+k) mod N]
    for (int j = tid; j < BATCH * (ITILE + 2); j += THREADS) {
        int b = j / (ITILE + 2);
        int k = j - b * (ITILE + 2);
        int gi = (i0 - 1 + k) & N_MASK;
        sxT[k][b] = x[b * N_CELLS + gi];
    }

    // Rearrange + pre-scale by 2/3.
    const float s = 2.0f / 3.0f;
    float tmp[12] = {wa.x, wa.y, wa.z, wa.w,
                     wb.x, wb.y, wb.z, wb.w,
                     wc.x, wc.y, wc.z, wc.w};
    float w0[4], w1[4], w2[4], bb[4];
    #pragma unroll
    for (int j = 0; j < 4; j++) {
        w0[j] = tmp[3 * j + 0] * s;
        w1[j] = tmp[3 * j + 1] * s;
        w2[j] = tmp[3 * j + 2] * s;
    }
    bb[0] = bv.x * s; bb[1] = bv.y * s; bb[2] = bv.z * s; bb[3] = bv.w * s;

    __syncthreads();

    float* outp = out + (size_t)i * NUM_CLASSES + c0;
    const size_t bstride = (size_t)N_CELLS * NUM_CLASSES;

    #pragma unroll 8
    for (int b = 0; b < BATCH; b += 4) {
        // One LDS.128 per tap covers 4 batches.
        float4 l4 = *reinterpret_cast<const float4*>(&sxT[it][b]);
        float4 c4 = *reinterpret_cast<const float4*>(&sxT[it + 1][b]);
        float4 r4 = *reinterpret_cast<const float4*>(&sxT[it + 2][b]);

        float ls[4] = {l4.x, l4.y, l4.z, l4.w};
        float cs[4] = {c4.x, c4.y, c4.z, c4.w};
        float rs[4] = {r4.x, r4.y, r4.z, r4.w};

        #pragma unroll
        for (int u = 0; u < 4; u++) {
            float o[4];
            #pragma unroll
            for (int j = 0; j < 4; j++) {
                float acc = fmaf(ls[u], w0[j],
                            fmaf(cs[u], w1[j],
                            fmaf(rs[u], w2[j], bb[j])));
                o[j] = 1.7159f * tanh_fast(acc);
            }
            st_cs_f4(outp + (size_t)(b + u) * bstride,
                     make_float4(o[0], o[1], o[2], o[3]));
        }
    }
}

extern "C" void kernel_launch(void* const* d_in, const int* in_sizes, int n_in,
                              void* d_out, int out_size) {
    const float* x    = (const float*)d_in[0];
    const float* w    = (const float*)d_in[1];
    const float* bias = (const float*)d_in[2];
    float* out = (float*)d_out;

    dim3 grid(N_CELLS / ITILE);   // 1024 CTAs
    dim3 block(THREADS);
    mcnl_kernel<<<grid, block>>>(x, w, bias, out);
}